// round 6
// baseline (speedup 1.0000x reference)
#include <cuda_runtime.h>
#include <cuda_fp16.h>
#include <cstdint>

#define NB 32
#define NL 2048
#define ND 1024
#define NROWS (NB * NL)   // 65536

// scores GEMM tiling
#define BM 256
#define BN 128
#define BK 32
#define NTHREADS 512
#define NKIT (ND / BK)          // 32
#define BUF_STRIDE 24576        // A 16KB + B 8KB per buffer
#define SMEM_BYTES (2 * BUF_STRIDE)
#define NTILES (ND / BN)        // 8
#define MTILES (NROWS / BM)     // 256

// ---------------- scratch ----------------
__device__ float g_ht[NB * ND];                 // 128 KB
__device__ float g_partial[NTILES * NROWS];     // 2 MB

// ---------------- helpers ----------------
__device__ __forceinline__ uint32_t smem_u32(const void* p) {
    uint32_t a;
    asm("{ .reg .u64 t; cvta.to.shared.u64 t, %1; cvt.u32.u64 %0, t; }" : "=r"(a) : "l"(p));
    return a;
}
__device__ __forceinline__ uint32_t pack_h2(float a, float b) {
    __half2 h = __floats2half2_rn(a, b);
    return *reinterpret_cast<uint32_t*>(&h);
}
__device__ __forceinline__ void ldsm4(uint32_t* r, uint32_t addr) {
    asm volatile("ldmatrix.sync.aligned.m8n8.x4.shared.b16 {%0,%1,%2,%3}, [%4];"
                 : "=r"(r[0]), "=r"(r[1]), "=r"(r[2]), "=r"(r[3]) : "r"(addr));
}
__device__ __forceinline__ void mma16816(float* c, const uint32_t* a, uint32_t b0, uint32_t b1) {
    asm volatile("mma.sync.aligned.m16n8k16.row.col.f32.f16.f16.f32 "
                 "{%0,%1,%2,%3}, {%4,%5,%6,%7}, {%8,%9}, {%0,%1,%2,%3};"
                 : "+f"(c[0]), "+f"(c[1]), "+f"(c[2]), "+f"(c[3])
                 : "r"(a[0]), "r"(a[1]), "r"(a[2]), "r"(a[3]), "r"(b0), "r"(b1));
}

// ---------------- K0: ht_proj[b,k] = sum_d x[b,d]*Wa[k,d] (fp32) ----------------
__global__ void ht_kernel(const float* __restrict__ x, const float* __restrict__ wa) {
    int b = blockIdx.x;
    int warp = threadIdx.x >> 5, lane = threadIdx.x & 31;
    const float* xr = x + b * ND;
    for (int k = warp; k < ND; k += 8) {
        const float* wr = wa + (size_t)k * (2 * ND);
        float acc = 0.f;
        #pragma unroll 8
        for (int d = lane; d < ND; d += 32) acc += xr[d] * wr[d];
        #pragma unroll
        for (int o = 16; o; o >>= 1) acc += __shfl_xor_sync(0xFFFFFFFFu, acc, o);
        if (lane == 0) g_ht[b * ND + k] = acc;
    }
}

// ---------------- K1: scores partials via fp16 mma.sync GEMM ----------------
// grid (MTILES, NTILES), 512 threads. C[BM,BN] = ctx_tile * Wa_s_tile^T (Wa scaled x64)
__global__ void __launch_bounds__(NTHREADS, 1) scores_kernel(
    const float* __restrict__ ctx, const float* __restrict__ wa,
    const float* __restrict__ va) {
    extern __shared__ char smem[];
    const uint32_t sbase = smem_u32(smem);

    const int tid = threadIdx.x;
    const int lane = tid & 31, wid = tid >> 5;
    const int wm = wid >> 2, wn = wid & 3;         // 4x4 warps, warp tile 64x32
    const int g = lane >> 2, tig = lane & 3;

    const int mtile = blockIdx.x, ntile = blockIdx.y;
    const int rbase = mtile * BM;
    const int nbase = ntile * BN;
    const int b = rbase >> 11;                      // 2048 rows per batch; BM=256 divides

    // --- gmem load assignment (per thread: 2 A-chunks + 1 B-chunk, 8 halves each) ---
    const int arow = tid >> 2;          // 0..127 (+128 for second chunk)
    const int akc  = tid & 3;           // 16B chunk within 64B row
    const uint32_t offA0 = arow * 64 + ((akc ^ (arow & 3)) << 4);
    const uint32_t offA1 = offA0 + 128 * 64;
    const uint32_t offB  = 16384 + offA0;   // same row/kc pattern for B

    const float* gA0 = ctx + (size_t)(rbase + arow) * ND + akc * 8;
    const float* gA1 = gA0 + (size_t)128 * ND;
    const float* gB  = wa + (size_t)(nbase + arow) * (2 * ND) + ND + akc * 8;

    // --- ldmatrix lane addresses ---
    const int aRow = wm * 64 + ((lane >> 3) & 1) * 8 + (lane & 7);
    const int bRow = wn * 32 + ((lane >> 4) & 1) * 8 + (lane & 7);
    uint32_t aSwz[2], bSwz[2];
    #pragma unroll
    for (int ks = 0; ks < 2; ks++) {
        aSwz[ks] = (uint32_t)(((ks * 2 + (lane >> 4)) ^ (lane & 3)) << 4);
        bSwz[ks] = (uint32_t)(((ks * 2 + ((lane >> 3) & 1)) ^ (lane & 3)) << 4);
    }
    const uint32_t aAddr0 = sbase + aRow * 64;
    const uint32_t bAddr0 = sbase + 16384 + bRow * 64;

    float c[4][4][4];
    #pragma unroll
    for (int i = 0; i < 4; i++)
        #pragma unroll
        for (int j = 0; j < 4; j++)
            #pragma unroll
            for (int q = 0; q < 4; q++) c[i][j][q] = 0.f;

    uint32_t pa0[4], pa1[4], pb[4];

    // prologue: load k-chunk 0
    {
        float4 f0 = *(const float4*)(gA0);
        float4 f1 = *(const float4*)(gA0 + 4);
        pa0[0] = pack_h2(f0.x, f0.y); pa0[1] = pack_h2(f0.z, f0.w);
        pa0[2] = pack_h2(f1.x, f1.y); pa0[3] = pack_h2(f1.z, f1.w);
        f0 = *(const float4*)(gA1); f1 = *(const float4*)(gA1 + 4);
        pa1[0] = pack_h2(f0.x, f0.y); pa1[1] = pack_h2(f0.z, f0.w);
        pa1[2] = pack_h2(f1.x, f1.y); pa1[3] = pack_h2(f1.z, f1.w);
        f0 = *(const float4*)(gB);  f1 = *(const float4*)(gB + 4);
        pb[0] = pack_h2(f0.x * 64.f, f0.y * 64.f); pb[1] = pack_h2(f0.z * 64.f, f0.w * 64.f);
        pb[2] = pack_h2(f1.x * 64.f, f1.y * 64.f); pb[3] = pack_h2(f1.z * 64.f, f1.w * 64.f);
    }
    *(uint4*)(smem + offA0) = make_uint4(pa0[0], pa0[1], pa0[2], pa0[3]);
    *(uint4*)(smem + offA1) = make_uint4(pa1[0], pa1[1], pa1[2], pa1[3]);
    *(uint4*)(smem + offB)  = make_uint4(pb[0], pb[1], pb[2], pb[3]);
    __syncthreads();

    for (int ck = 0; ck < NKIT; ck++) {
        // prefetch next k-chunk into registers
        if (ck + 1 < NKIT) {
            const float* a0 = gA0 + (ck + 1) * BK;
            const float* a1 = gA1 + (ck + 1) * BK;
            const float* bb = gB + (ck + 1) * BK;
            float4 f0 = *(const float4*)(a0);
            float4 f1 = *(const float4*)(a0 + 4);
            pa0[0] = pack_h2(f0.x, f0.y); pa0[1] = pack_h2(f0.z, f0.w);
            pa0[2] = pack_h2(f1.x, f1.y); pa0[3] = pack_h2(f1.z, f1.w);
            f0 = *(const float4*)(a1); f1 = *(const float4*)(a1 + 4);
            pa1[0] = pack_h2(f0.x, f0.y); pa1[1] = pack_h2(f0.z, f0.w);
            pa1[2] = pack_h2(f1.x, f1.y); pa1[3] = pack_h2(f1.z, f1.w);
            f0 = *(const float4*)(bb); f1 = *(const float4*)(bb + 4);
            pb[0] = pack_h2(f0.x * 64.f, f0.y * 64.f); pb[1] = pack_h2(f0.z * 64.f, f0.w * 64.f);
            pb[2] = pack_h2(f1.x * 64.f, f1.y * 64.f); pb[3] = pack_h2(f1.z * 64.f, f1.w * 64.f);
        }

        const uint32_t bufOff = (uint32_t)(ck & 1) * BUF_STRIDE;
        #pragma unroll
        for (int ks = 0; ks < 2; ks++) {
            uint32_t af[4][4];
            #pragma unroll
            for (int mt = 0; mt < 4; mt++)
                ldsm4(af[mt], aAddr0 + bufOff + mt * 1024 + aSwz[ks]);
            uint32_t bf[2][4];
            #pragma unroll
            for (int gb = 0; gb < 2; gb++)
                ldsm4(bf[gb], bAddr0 + bufOff + gb * 1024 + bSwz[ks]);
            #pragma unroll
            for (int mt = 0; mt < 4; mt++)
                #pragma unroll
                for (int n8 = 0; n8 < 4; n8++)
                    mma16816(c[mt][n8], af[mt], bf[n8 >> 1][(n8 & 1) * 2],
                             bf[n8 >> 1][(n8 & 1) * 2 + 1]);
        }

        if (ck + 1 < NKIT) {
            char* s = smem + ((ck + 1) & 1) * BUF_STRIDE;
            *(uint4*)(s + offA0) = make_uint4(pa0[0], pa0[1], pa0[2], pa0[3]);
            *(uint4*)(s + offA1) = make_uint4(pa1[0], pa1[1], pa1[2], pa1[3]);
            *(uint4*)(s + offB)  = make_uint4(pb[0], pb[1], pb[2], pb[3]);
        }
        __syncthreads();
    }

    // ---- epilogue: partial scores: p[row] = sum_col va[k]*tanh(ht[b,k] + C/64) ----
    // Each warp (wm, wn) holds rows wm*64..+63 and cols wn*32..+31. Reduce over
    // wn through smem (4 warps share the same rows) -> single deterministic store.
    float* sht  = (float*)smem;                 // [BN]
    float* sva  = sht + BN;                     // [BN]
    float* sred = (float*)(smem + 4096);        // [4][BM] = 4 KB
    for (int i = tid; i < BN; i += NTHREADS) {
        sht[i] = g_ht[b * ND + nbase + i];
        sva[i] = va[nbase + i];
    }
    __syncthreads();

    const float inv = 1.0f / 64.0f;
    #pragma unroll
    for (int mt = 0; mt < 4; mt++) {
        float p0 = 0.f, p1 = 0.f;
        #pragma unroll
        for (int n8 = 0; n8 < 4; n8++) {
            #pragma unroll
            for (int j = 0; j < 2; j++) {
                int col = wn * 32 + n8 * 8 + tig * 2 + j;
                float hv = sht[col], vv = sva[col];
                p0 += vv * tanhf(hv + c[mt][n8][j] * inv);
                p1 += vv * tanhf(hv + c[mt][n8][2 + j] * inv);
            }
        }
        p0 += __shfl_xor_sync(0xFFFFFFFFu, p0, 1);
        p0 += __shfl_xor_sync(0xFFFFFFFFu, p0, 2);
        p1 += __shfl_xor_sync(0xFFFFFFFFu, p1, 1);
        p1 += __shfl_xor_sync(0xFFFFFFFFu, p1, 2);
        if (tig == 0) {
            int rl = wm * 64 + mt * 16 + g;
            sred[wn * BM + rl]     = p0;
            sred[wn * BM + rl + 8] = p1;
        }
    }
    __syncthreads();
    for (int i = tid; i < BM; i += NTHREADS) {
        float s = sred[i] + sred[BM + i] + sred[2 * BM + i] + sred[3 * BM + i];
        g_partial[(size_t)ntile * NROWS + rbase + i] = s;
    }
}

// ---------------- K2: sum partials + softmax -> out[NB*ND ..] ----------------
__global__ void softmax_kernel(float* __restrict__ out) {
    __shared__ float red[256];
    int b = blockIdx.x, tid = threadIdx.x;
    float v[8], mx = -1e30f;
    #pragma unroll
    for (int i = 0; i < 8; i++) {
        int idx = b * NL + i * 256 + tid;
        float s = 0.f;
        #pragma unroll
        for (int p = 0; p < NTILES; p++) s += g_partial[(size_t)p * NROWS + idx];
        v[i] = s;
        mx = fmaxf(mx, s);
    }
    red[tid] = mx; __syncthreads();
    for (int o = 128; o; o >>= 1) { if (tid < o) red[tid] = fmaxf(red[tid], red[tid + o]); __syncthreads(); }
    mx = red[0]; __syncthreads();
    float sum = 0.f;
    #pragma unroll
    for (int i = 0; i < 8; i++) { v[i] = expf(v[i] - mx); sum += v[i]; }
    red[tid] = sum; __syncthreads();
    for (int o = 128; o; o >>= 1) { if (tid < o) red[tid] += red[tid + o]; __syncthreads(); }
    float invs = 1.f / red[0];
    #pragma unroll
    for (int i = 0; i < 8; i++) out[NB * ND + b * NL + i * 256 + tid] = v[i] * invs;
}

// ---------------- K3: weighted[b,d] = sum_l attn[b,l]*context[b,l,d] ----------------
__global__ void weighted_kernel(const float* __restrict__ ctx, float* __restrict__ out) {
    __shared__ float sa[NL];
    int b = blockIdx.y, dc = blockIdx.x, tid = threadIdx.x;
    for (int i = tid; i < NL; i += 256) sa[i] = out[NB * ND + b * NL + i];
    __syncthreads();
    int d = dc * 256 + tid;
    const float* cb = ctx + (size_t)b * NL * ND + d;
    float acc = 0.f;
    #pragma unroll 8
    for (int l = 0; l < NL; l++) acc += sa[l] * cb[(size_t)l * ND];
    out[b * ND + d] = acc;
}

// ---------------- launch ----------------
extern "C" void kernel_launch(void* const* d_in, const int* in_sizes, int n_in,
                              void* d_out, int out_size) {
    const float* x   = (const float*)d_in[0];
    const float* ctx = (const float*)d_in[1];
    const float* wa  = (const float*)d_in[2];
    const float* va  = (const float*)d_in[3];
    float* out = (float*)d_out;

    static bool attr_set = false;
    if (!attr_set) {
        cudaFuncSetAttribute(scores_kernel, cudaFuncAttributeMaxDynamicSharedMemorySize, SMEM_BYTES);
        attr_set = true;
    }

    ht_kernel<<<NB, 256>>>(x, wa);
    dim3 g1(MTILES, NTILES);
    scores_kernel<<<g1, NTHREADS, SMEM_BYTES>>>(ctx, wa, va);
    softmax_kernel<<<NB, 256>>>(out);
    dim3 g3(ND / 256, NB);
    weighted_kernel<<<g3, 256>>>(ctx, out);
}

// round 7
// speedup vs baseline: 1.2135x; 1.2135x over previous
#include <cuda_runtime.h>
#include <cuda_fp16.h>
#include <cstdint>

#define NB 32
#define NL 2048
#define ND 1024
#define NROWS (NB * NL)   // 65536

// scores GEMM tiling
#define BM 128
#define BN 256
#define BK 64
#define NTHREADS 256
#define NKIT (ND / BK)            // 16
#define NSTAGE 3
#define A_BYTES (BM * 128)        // 16 KB  (128 rows x 64 halves)
#define B_BYTES (BN * 128)        // 32 KB
#define STAGE_BYTES (A_BYTES + B_BYTES)
#define SMEM_BYTES (NSTAGE * STAGE_BYTES)   // 144 KB
#define NTILES (ND / BN)          // 4
#define MTILES (NROWS / BM)       // 512

#define LCH 16                    // weighted split-L chunks

// ---------------- scratch ----------------
__device__ __half g_ctx_h[(size_t)NROWS * ND];   // 128 MB
__device__ __half g_wb_h[ND * ND];               // 2 MB (Wa_s * 64, [n][d])
__device__ float g_ht[NB * ND];                  // 128 KB
__device__ float g_partial[NTILES * NROWS];      // 1 MB
__device__ float g_wpart[LCH][NB][ND];           // 2 MB

// ---------------- helpers ----------------
__device__ __forceinline__ uint32_t smem_u32(const void* p) {
    uint32_t a;
    asm("{ .reg .u64 t; cvta.to.shared.u64 t, %1; cvt.u32.u64 %0, t; }" : "=r"(a) : "l"(p));
    return a;
}
__device__ __forceinline__ void cpa16(uint32_t dst, const void* src) {
    asm volatile("cp.async.cg.shared.global [%0], [%1], 16;" :: "r"(dst), "l"(src));
}
__device__ __forceinline__ void cpa_commit() {
    asm volatile("cp.async.commit_group;" ::: "memory");
}
__device__ __forceinline__ void cpa_wait1() {
    asm volatile("cp.async.wait_group 1;" ::: "memory");
}
__device__ __forceinline__ void ldsm4(uint32_t* r, uint32_t addr) {
    asm volatile("ldmatrix.sync.aligned.m8n8.x4.shared.b16 {%0,%1,%2,%3}, [%4];"
                 : "=r"(r[0]), "=r"(r[1]), "=r"(r[2]), "=r"(r[3]) : "r"(addr));
}
__device__ __forceinline__ void mma16816(float* c, const uint32_t* a, uint32_t b0, uint32_t b1) {
    asm volatile("mma.sync.aligned.m16n8k16.row.col.f32.f16.f16.f32 "
                 "{%0,%1,%2,%3}, {%4,%5,%6,%7}, {%8,%9}, {%0,%1,%2,%3};"
                 : "+f"(c[0]), "+f"(c[1]), "+f"(c[2]), "+f"(c[3])
                 : "r"(a[0]), "r"(a[1]), "r"(a[2]), "r"(a[3]), "r"(b0), "r"(b1));
}
__device__ __forceinline__ uint32_t pack2(float a, float b) {
    __half2 h = __floats2half2_rn(a, b);
    return *reinterpret_cast<uint32_t*>(&h);
}

// ---------------- P0: convert context fp32 -> fp16 ----------------
__global__ void ctx_convert(const float* __restrict__ ctx) {
    size_t i = (size_t)blockIdx.x * 256 + threadIdx.x;       // group id (float4)
    const float4* src = (const float4*)ctx;
    uint2* dst = (uint2*)g_ctx_h;
    #pragma unroll
    for (int j = 0; j < 4; j++) {
        size_t g = i + (size_t)j * 4194304;                  // 16M groups total
        float4 v = src[g];
        dst[g] = make_uint2(pack2(v.x, v.y), pack2(v.z, v.w));
    }
}

// ---------------- P1: convert Wa_s (scaled x64) -> fp16 ----------------
__global__ void wb_convert(const float* __restrict__ wa) {
    int n = blockIdx.x;
    int d4 = threadIdx.x * 4;
    const float* src = wa + (size_t)n * (2 * ND) + ND + d4;
    float4 v = *(const float4*)src;
    uint2* dst = (uint2*)(g_wb_h + (size_t)n * ND);
    dst[threadIdx.x] = make_uint2(pack2(v.x * 64.f, v.y * 64.f),
                                  pack2(v.z * 64.f, v.w * 64.f));
}

// ---------------- K0: ht_proj[b,k] = sum_d x[b,d]*Wa[k,d] (fp32) ----------------
__global__ void ht_kernel(const float* __restrict__ x, const float* __restrict__ wa) {
    int b = blockIdx.x;
    int warp = threadIdx.x >> 5, lane = threadIdx.x & 31;
    const float* xr = x + b * ND;
    for (int k = warp; k < ND; k += 8) {
        const float* wr = wa + (size_t)k * (2 * ND);
        float acc = 0.f;
        #pragma unroll 8
        for (int d = lane; d < ND; d += 32) acc += xr[d] * wr[d];
        #pragma unroll
        for (int o = 16; o; o >>= 1) acc += __shfl_xor_sync(0xFFFFFFFFu, acc, o);
        if (lane == 0) g_ht[b * ND + k] = acc;
    }
}

// ---------------- K1: scores partials via fp16 mma.sync GEMM ----------------
// grid 2048: mtile = bid>>2, ntile = bid&3 (adjacent bids share A rows -> L2 reuse)
// 256 thr, warps 2x4, warp tile 64x64, BK=64, 3-stage cp.async, SW128-style swizzle.
__global__ void __launch_bounds__(NTHREADS, 1) scores_kernel(const float* __restrict__ va) {
    extern __shared__ char smem[];
    const uint32_t sbase = smem_u32(smem);

    const int tid = threadIdx.x;
    const int lane = tid & 31, wid = tid >> 5;
    const int wm = wid >> 2, wn = wid & 3;       // 2 x 4 warps
    const int g = lane >> 2, tig = lane & 3;
    const int lane7 = lane & 7;
    const int cSelA = lane >> 4;                 // 0/1
    const int cSelB = (lane >> 3) & 1;           // 0/1

    const int mtile = blockIdx.x >> 2, ntile = blockIdx.x & 3;
    const int rbase = mtile * BM;
    const int nbase = ntile * BN;
    const int b = rbase >> 11;

    const __half* gA = g_ctx_h + (size_t)rbase * ND;
    const __half* gB = g_wb_h + (size_t)nbase * ND;

    // cp.async per-thread assignments
    // A: 1024 16B-chunks: id = tid*4+i -> row=id>>3, c=id&7
    // B: 2048 16B-chunks: id = tid*8+i
    // dst offset = row*128 + ((c ^ (row&7))<<4)
    uint32_t aDst[4], bDst[8];
    uint32_t aSrcOff[4], bSrcOff[8];             // in halves, relative to (rowbase, k-chunk)
    #pragma unroll
    for (int i = 0; i < 4; i++) {
        int id = tid * 4 + i, row = id >> 3, c = id & 7;
        aDst[i] = row * 128 + ((c ^ (row & 7)) << 4);
        aSrcOff[i] = row * ND + c * 8;
    }
    #pragma unroll
    for (int i = 0; i < 8; i++) {
        int id = tid * 8 + i, row = id >> 3, c = id & 7;
        bDst[i] = A_BYTES + row * 128 + ((c ^ (row & 7)) << 4);
        bSrcOff[i] = row * ND + c * 8;
    }

    // ldmatrix base offsets
    const int aRow = wm * 64 + ((lane >> 3) & 1) * 8 + lane7;           // + mt*16
    const uint32_t aOff = (uint32_t)aRow * 128;
    uint32_t bOff[4];
    #pragma unroll
    for (int i = 0; i < 4; i++)
        bOff[i] = (uint32_t)(wn * 64 + i * 16 + ((lane >> 4) & 1) * 8 + lane7) * 128 + A_BYTES;

    float c[4][8][4];
    #pragma unroll
    for (int i = 0; i < 4; i++)
        #pragma unroll
        for (int j = 0; j < 8; j++)
            #pragma unroll
            for (int q = 0; q < 4; q++) c[i][j][q] = 0.f;

    // prologue: fill stages 0,1 (k-chunks 0,1)
    #pragma unroll
    for (int s = 0; s < 2; s++) {
        uint32_t st = sbase + s * STAGE_BYTES;
        const __half* a = gA + s * BK;
        const __half* bb = gB + s * BK;
        #pragma unroll
        for (int i = 0; i < 4; i++) cpa16(st + aDst[i], a + aSrcOff[i]);
        #pragma unroll
        for (int i = 0; i < 8; i++) cpa16(st + bDst[i], bb + bSrcOff[i]);
        cpa_commit();
    }

    int stage = 0;
    for (int ck = 0; ck < NKIT; ck++) {
        cpa_wait1();
        __syncthreads();

        // issue k-chunk ck+2 into stage (stage+2)%3 (all warps done reading it)
        if (ck + 2 < NKIT) {
            int s2 = stage + 2; if (s2 >= 3) s2 -= 3;
            uint32_t st = sbase + s2 * STAGE_BYTES;
            const __half* a = gA + (ck + 2) * BK;
            const __half* bb = gB + (ck + 2) * BK;
            #pragma unroll
            for (int i = 0; i < 4; i++) cpa16(st + aDst[i], a + aSrcOff[i]);
            #pragma unroll
            for (int i = 0; i < 8; i++) cpa16(st + bDst[i], bb + bSrcOff[i]);
        }
        cpa_commit();

        const uint32_t sA = sbase + stage * STAGE_BYTES;
        #pragma unroll
        for (int ks = 0; ks < 4; ks++) {
            uint32_t aSwz = (uint32_t)(((ks * 2 + cSelA) ^ lane7) << 4);
            uint32_t bSwz = (uint32_t)(((ks * 2 + cSelB) ^ lane7) << 4);
            uint32_t af[4][4], bf[4][4];
            #pragma unroll
            for (int mt = 0; mt < 4; mt++)
                ldsm4(af[mt], sA + aOff + mt * 2048 + aSwz);
            #pragma unroll
            for (int i = 0; i < 4; i++)
                ldsm4(bf[i], sA + bOff[i] + bSwz);
            #pragma unroll
            for (int mt = 0; mt < 4; mt++)
                #pragma unroll
                for (int n8 = 0; n8 < 8; n8++)
                    mma16816(c[mt][n8], af[mt], bf[n8 >> 1][(n8 & 1) * 2],
                             bf[n8 >> 1][(n8 & 1) * 2 + 1]);
        }
        stage++; if (stage >= 3) stage = 0;
    }
    __syncthreads();

    // ---- epilogue: p[row] = sum_col va[k]*tanh(ht[b,k] + C/64), cross-wn smem reduce ----
    float* sht  = (float*)smem;                 // [BN]
    float* sva  = sht + BN;                     // [BN]
    float* sred = sva + BN;                     // [4][BM]
    for (int i = tid; i < BN; i += NTHREADS) {
        sht[i] = g_ht[b * ND + nbase + i];
        sva[i] = va[nbase + i];
    }
    __syncthreads();

    const float inv = 1.0f / 64.0f;
    #pragma unroll
    for (int mt = 0; mt < 4; mt++) {
        float p0 = 0.f, p1 = 0.f;
        #pragma unroll
        for (int n8 = 0; n8 < 8; n8++) {
            #pragma unroll
            for (int j = 0; j < 2; j++) {
                int col = wn * 64 + n8 * 8 + tig * 2 + j;
                float hv = sht[col], vv = sva[col];
                p0 += vv * tanhf(hv + c[mt][n8][j] * inv);
                p1 += vv * tanhf(hv + c[mt][n8][2 + j] * inv);
            }
        }
        p0 += __shfl_xor_sync(0xFFFFFFFFu, p0, 1);
        p0 += __shfl_xor_sync(0xFFFFFFFFu, p0, 2);
        p1 += __shfl_xor_sync(0xFFFFFFFFu, p1, 1);
        p1 += __shfl_xor_sync(0xFFFFFFFFu, p1, 2);
        if (tig == 0) {
            int rl = wm * 64 + mt * 16 + g;
            sred[wn * BM + rl]     = p0;
            sred[wn * BM + rl + 8] = p1;
        }
    }
    __syncthreads();
    for (int i = tid; i < BM; i += NTHREADS) {
        float s = sred[i] + sred[BM + i] + sred[2 * BM + i] + sred[3 * BM + i];
        g_partial[(size_t)ntile * NROWS + rbase + i] = s;
    }
}

// ---------------- K2: sum partials + softmax -> out[NB*ND ..] ----------------
__global__ void softmax_kernel(float* __restrict__ out) {
    __shared__ float red[256];
    int b = blockIdx.x, tid = threadIdx.x;
    float v[8], mx = -1e30f;
    #pragma unroll
    for (int i = 0; i < 8; i++) {
        int idx = b * NL + i * 256 + tid;
        float s = 0.f;
        #pragma unroll
        for (int p = 0; p < NTILES; p++) s += g_partial[(size_t)p * NROWS + idx];
        v[i] = s;
        mx = fmaxf(mx, s);
    }
    red[tid] = mx; __syncthreads();
    for (int o = 128; o; o >>= 1) { if (tid < o) red[tid] = fmaxf(red[tid], red[tid + o]); __syncthreads(); }
    mx = red[0]; __syncthreads();
    float sum = 0.f;
    #pragma unroll
    for (int i = 0; i < 8; i++) { v[i] = expf(v[i] - mx); sum += v[i]; }
    red[tid] = sum; __syncthreads();
    for (int o = 128; o; o >>= 1) { if (tid < o) red[tid] += red[tid + o]; __syncthreads(); }
    float invs = 1.f / red[0];
    #pragma unroll
    for (int i = 0; i < 8; i++) out[NB * ND + b * NL + i * 256 + tid] = v[i] * invs;
}

// ---------------- K3a: weighted partials over L-chunks ----------------
__global__ void weighted_part(const float* __restrict__ ctx, const float* __restrict__ out) {
    __shared__ float sa[NL / LCH];   // 128
    int lc = blockIdx.x, b = blockIdx.y, tid = threadIdx.x;
    for (int i = tid; i < NL / LCH; i += 256)
        sa[i] = out[NB * ND + b * NL + lc * (NL / LCH) + i];
    __syncthreads();
    const float4* cb = (const float4*)(ctx + ((size_t)b * NL + lc * (NL / LCH)) * ND) + tid;
    float4 acc = make_float4(0.f, 0.f, 0.f, 0.f);
    #pragma unroll 4
    for (int l = 0; l < NL / LCH; l++) {
        float4 v = cb[l * (ND / 4)];
        float a = sa[l];
        acc.x += a * v.x; acc.y += a * v.y; acc.z += a * v.z; acc.w += a * v.w;
    }
    *(float4*)(&g_wpart[lc][b][tid * 4]) = acc;
}

// ---------------- K3b: reduce partials -> out[0 .. NB*ND) ----------------
__global__ void weighted_reduce(float* __restrict__ out) {
    int b = blockIdx.x, tid = threadIdx.x;
    #pragma unroll
    for (int j = 0; j < 4; j++) {
        int d = j * 256 + tid;
        float s = 0.f;
        #pragma unroll
        for (int lc = 0; lc < LCH; lc++) s += g_wpart[lc][b][d];
        out[b * ND + d] = s;
    }
}

// ---------------- launch ----------------
extern "C" void kernel_launch(void* const* d_in, const int* in_sizes, int n_in,
                              void* d_out, int out_size) {
    const float* x   = (const float*)d_in[0];
    const float* ctx = (const float*)d_in[1];
    const float* wa  = (const float*)d_in[2];
    const float* va  = (const float*)d_in[3];
    float* out = (float*)d_out;

    cudaFuncSetAttribute(scores_kernel, cudaFuncAttributeMaxDynamicSharedMemorySize, SMEM_BYTES);

    ctx_convert<<<16384, 256>>>(ctx);
    wb_convert<<<ND, 256>>>(wa);
    ht_kernel<<<NB, 256>>>(x, wa);
    scores_kernel<<<MTILES * NTILES, NTHREADS, SMEM_BYTES>>>(va);
    softmax_kernel<<<NB, 256>>>(out);
    dim3 g3(LCH, NB);
    weighted_part<<<g3, 256>>>(ctx, out);
    weighted_reduce<<<NB, 256>>>(out);
}

// round 8
// speedup vs baseline: 1.2231x; 1.0080x over previous
#include <cuda_runtime.h>
#include <cuda_fp16.h>
#include <cstdint>

#define NB 32
#define NL 2048
#define ND 1024
#define NROWS (NB * NL)   // 65536

// scores GEMM tiling
#define BM 128
#define BN 256
#define BK 64
#define NTHREADS 256
#define NKIT (ND / BK)            // 16
#define NSTAGE 3
#define A_BYTES (BM * 128)        // 16 KB
#define B_BYTES (BN * 128)        // 32 KB
#define STAGE_BYTES (A_BYTES + B_BYTES)
#define SMEM_BYTES (NSTAGE * STAGE_BYTES)   // 144 KB
#define NTILES (ND / BN)          // 4
#define MTILES (NROWS / BM)       // 512

#define LCH 16                    // weighted split-L chunks

// ---------------- scratch ----------------
__device__ __half g_ctx_h[(size_t)NROWS * ND];   // 128 MB
__device__ __half g_wb_h[ND * ND];               // 2 MB (Wa_s * 64, [n][d])
__device__ float g_ht[NB * ND];                  // 128 KB
__device__ float g_partial[NTILES * NROWS];      // 1 MB
__device__ float g_wpart[LCH][NB][ND];           // 2 MB

// ---------------- helpers ----------------
__device__ __forceinline__ uint32_t smem_u32(const void* p) {
    uint32_t a;
    asm("{ .reg .u64 t; cvta.to.shared.u64 t, %1; cvt.u32.u64 %0, t; }" : "=r"(a) : "l"(p));
    return a;
}
__device__ __forceinline__ void cpa16(uint32_t dst, const void* src) {
    asm volatile("cp.async.cg.shared.global [%0], [%1], 16;" :: "r"(dst), "l"(src));
}
__device__ __forceinline__ void cpa_commit() {
    asm volatile("cp.async.commit_group;" ::: "memory");
}
__device__ __forceinline__ void cpa_wait1() {
    asm volatile("cp.async.wait_group 1;" ::: "memory");
}
__device__ __forceinline__ void ldsm4(uint32_t* r, uint32_t addr) {
    asm volatile("ldmatrix.sync.aligned.m8n8.x4.shared.b16 {%0,%1,%2,%3}, [%4];"
                 : "=r"(r[0]), "=r"(r[1]), "=r"(r[2]), "=r"(r[3]) : "r"(addr));
}
__device__ __forceinline__ void mma16816(float* c, const uint32_t* a, uint32_t b0, uint32_t b1) {
    asm volatile("mma.sync.aligned.m16n8k16.row.col.f32.f16.f16.f32 "
                 "{%0,%1,%2,%3}, {%4,%5,%6,%7}, {%8,%9}, {%0,%1,%2,%3};"
                 : "+f"(c[0]), "+f"(c[1]), "+f"(c[2]), "+f"(c[3])
                 : "r"(a[0]), "r"(a[1]), "r"(a[2]), "r"(a[3]), "r"(b0), "r"(b1));
}
__device__ __forceinline__ uint32_t pack2(float a, float b) {
    __half2 h = __floats2half2_rn(a, b);
    return *reinterpret_cast<uint32_t*>(&h);
}

// ---------------- P0: convert context fp32 -> fp16 (high-MLP stream) ----------------
__global__ void ctx_convert(const float* __restrict__ ctx) {
    size_t base = (size_t)blockIdx.x * 256 + threadIdx.x;    // 8192 blocks
    const float4* src = (const float4*)ctx;
    uint2* dst = (uint2*)g_ctx_h;
    #pragma unroll
    for (int j = 0; j < 8; j++) {
        size_t g = base + (size_t)j * 2097152;               // 16M float4 groups
        float4 v = src[g];
        dst[g] = make_uint2(pack2(v.x, v.y), pack2(v.z, v.w));
    }
}

// ---------------- P1: convert Wa_s (scaled x64) -> fp16 ----------------
__global__ void wb_convert(const float* __restrict__ wa) {
    int n = blockIdx.x;
    const float* src = wa + (size_t)n * (2 * ND) + ND + threadIdx.x * 4;
    float4 v = *(const float4*)src;
    uint2* dst = (uint2*)(g_wb_h + (size_t)n * ND);
    dst[threadIdx.x] = make_uint2(pack2(v.x * 64.f, v.y * 64.f),
                                  pack2(v.z * 64.f, v.w * 64.f));
}

// ---------------- K0: ht_proj[b,k] = sum_d x[b,d]*Wa[k,d] (fp32) ----------------
__global__ void ht_kernel(const float* __restrict__ x, const float* __restrict__ wa) {
    int b = blockIdx.x;
    int warp = threadIdx.x >> 5, lane = threadIdx.x & 31;
    const float* xr = x + b * ND;
    for (int k = warp; k < ND; k += 8) {
        const float* wr = wa + (size_t)k * (2 * ND);
        float acc = 0.f;
        #pragma unroll 8
        for (int d = lane; d < ND; d += 32) acc += xr[d] * wr[d];
        #pragma unroll
        for (int o = 16; o; o >>= 1) acc += __shfl_xor_sync(0xFFFFFFFFu, acc, o);
        if (lane == 0) g_ht[b * ND + k] = acc;
    }
}

// ---------------- K1: scores partials via fp16 mma.sync GEMM ----------------
// grid 2048: mtile = bid>>2, ntile = bid&3. 256 thr, warps 2x4, warp tile 64x64,
// BK=64, 3-stage cp.async, ks-level fragment double buffering.
__global__ void __launch_bounds__(NTHREADS, 1) scores_kernel(const float* __restrict__ va) {
    extern __shared__ char smem[];
    const uint32_t sbase = smem_u32(smem);

    const int tid = threadIdx.x;
    const int lane = tid & 31, wid = tid >> 5;
    const int wm = wid >> 2, wn = wid & 3;       // 2 x 4 warps
    const int g = lane >> 2, tig = lane & 3;
    const int lane7 = lane & 7;
    const int cSelA = lane >> 4;                 // 0/1
    const int cSelB = (lane >> 3) & 1;           // 0/1

    const int mtile = blockIdx.x >> 2, ntile = blockIdx.x & 3;
    const int rbase = mtile * BM;
    const int nbase = ntile * BN;
    const int b = rbase >> 11;

    const __half* gA = g_ctx_h + (size_t)rbase * ND;
    const __half* gB = g_wb_h + (size_t)nbase * ND;

    // cp.async per-thread assignments
    uint32_t aDst[4], bDst[8];
    uint32_t aSrcOff[4], bSrcOff[8];
    #pragma unroll
    for (int i = 0; i < 4; i++) {
        int id = tid * 4 + i, row = id >> 3, c = id & 7;
        aDst[i] = row * 128 + ((c ^ (row & 7)) << 4);
        aSrcOff[i] = row * ND + c * 8;
    }
    #pragma unroll
    for (int i = 0; i < 8; i++) {
        int id = tid * 8 + i, row = id >> 3, c = id & 7;
        bDst[i] = A_BYTES + row * 128 + ((c ^ (row & 7)) << 4);
        bSrcOff[i] = row * ND + c * 8;
    }

    // ldmatrix base offsets
    const int aRow = wm * 64 + ((lane >> 3) & 1) * 8 + lane7;
    const uint32_t aOff = (uint32_t)aRow * 128;
    uint32_t bOff[4];
    #pragma unroll
    for (int i = 0; i < 4; i++)
        bOff[i] = (uint32_t)(wn * 64 + i * 16 + ((lane >> 4) & 1) * 8 + lane7) * 128 + A_BYTES;

    float c[4][8][4];
    #pragma unroll
    for (int i = 0; i < 4; i++)
        #pragma unroll
        for (int j = 0; j < 8; j++)
            #pragma unroll
            for (int q = 0; q < 4; q++) c[i][j][q] = 0.f;

    // prologue: fill stages 0,1
    #pragma unroll
    for (int s = 0; s < 2; s++) {
        uint32_t st = sbase + s * STAGE_BYTES;
        const __half* a = gA + s * BK;
        const __half* bb = gB + s * BK;
        #pragma unroll
        for (int i = 0; i < 4; i++) cpa16(st + aDst[i], a + aSrcOff[i]);
        #pragma unroll
        for (int i = 0; i < 8; i++) cpa16(st + bDst[i], bb + bSrcOff[i]);
        cpa_commit();
    }

    uint32_t af[2][4][4], bf[2][4][4];
    int stage = 0;
    for (int ck = 0; ck < NKIT; ck++) {
        cpa_wait1();
        __syncthreads();

        // issue k-chunk ck+2 into stage (stage+2)%3
        if (ck + 2 < NKIT) {
            int s2 = stage + 2; if (s2 >= 3) s2 -= 3;
            uint32_t st = sbase + s2 * STAGE_BYTES;
            const __half* a = gA + (ck + 2) * BK;
            const __half* bb = gB + (ck + 2) * BK;
            #pragma unroll
            for (int i = 0; i < 4; i++) cpa16(st + aDst[i], a + aSrcOff[i]);
            #pragma unroll
            for (int i = 0; i < 8; i++) cpa16(st + bDst[i], bb + bSrcOff[i]);
        }
        cpa_commit();

        const uint32_t sA = sbase + stage * STAGE_BYTES;
        // load ks=0 fragments into buffer 0
        {
            uint32_t aSwz = (uint32_t)((cSelA ^ lane7) << 4);
            uint32_t bSwz = (uint32_t)((cSelB ^ lane7) << 4);
            #pragma unroll
            for (int mt = 0; mt < 4; mt++) ldsm4(af[0][mt], sA + aOff + mt * 2048 + aSwz);
            #pragma unroll
            for (int i = 0; i < 4; i++) ldsm4(bf[0][i], sA + bOff[i] + bSwz);
        }
        #pragma unroll
        for (int ks = 0; ks < 4; ks++) {
            const int cur = ks & 1, nxt = cur ^ 1;
            if (ks < 3) {   // prefetch fragments for ks+1 (independent of cur MMAs)
                uint32_t aSwz = (uint32_t)((((ks + 1) * 2 + cSelA) ^ lane7) << 4);
                uint32_t bSwz = (uint32_t)((((ks + 1) * 2 + cSelB) ^ lane7) << 4);
                #pragma unroll
                for (int mt = 0; mt < 4; mt++) ldsm4(af[nxt][mt], sA + aOff + mt * 2048 + aSwz);
                #pragma unroll
                for (int i = 0; i < 4; i++) ldsm4(bf[nxt][i], sA + bOff[i] + bSwz);
            }
            #pragma unroll
            for (int mt = 0; mt < 4; mt++)
                #pragma unroll
                for (int n8 = 0; n8 < 8; n8++)
                    mma16816(c[mt][n8], af[cur][mt], bf[cur][n8 >> 1][(n8 & 1) * 2],
                             bf[cur][n8 >> 1][(n8 & 1) * 2 + 1]);
        }
        stage++; if (stage >= 3) stage = 0;
    }
    __syncthreads();

    // ---- epilogue: p[row] = sum_col va[k]*tanh(ht[b,k] + C/64), cross-wn smem reduce ----
    float* sht  = (float*)smem;                 // [BN]
    float* sva  = sht + BN;                     // [BN]
    float* sred = sva + BN;                     // [4][BM]
    for (int i = tid; i < BN; i += NTHREADS) {
        sht[i] = g_ht[b * ND + nbase + i];
        sva[i] = va[nbase + i];
    }
    __syncthreads();

    const float inv = 1.0f / 64.0f;
    #pragma unroll
    for (int mt = 0; mt < 4; mt++) {
        float p0 = 0.f, p1 = 0.f;
        #pragma unroll
        for (int n8 = 0; n8 < 8; n8++) {
            #pragma unroll
            for (int j = 0; j < 2; j++) {
                int col = wn * 64 + n8 * 8 + tig * 2 + j;
                float hv = sht[col], vv = sva[col];
                p0 += vv * tanhf(hv + c[mt][n8][j] * inv);
                p1 += vv * tanhf(hv + c[mt][n8][2 + j] * inv);
            }
        }
        p0 += __shfl_xor_sync(0xFFFFFFFFu, p0, 1);
        p0 += __shfl_xor_sync(0xFFFFFFFFu, p0, 2);
        p1 += __shfl_xor_sync(0xFFFFFFFFu, p1, 1);
        p1 += __shfl_xor_sync(0xFFFFFFFFu, p1, 2);
        if (tig == 0) {
            int rl = wm * 64 + mt * 16 + g;
            sred[wn * BM + rl]     = p0;
            sred[wn * BM + rl + 8] = p1;
        }
    }
    __syncthreads();
    for (int i = tid; i < BM; i += NTHREADS) {
        float s = sred[i] + sred[BM + i] + sred[2 * BM + i] + sred[3 * BM + i];
        g_partial[(size_t)ntile * NROWS + rbase + i] = s;
    }
}

// ---------------- K2: sum partials + softmax -> out[NB*ND ..] ----------------
__global__ void softmax_kernel(float* __restrict__ out) {
    __shared__ float red[256];
    int b = blockIdx.x, tid = threadIdx.x;
    float v[8], mx = -1e30f;
    #pragma unroll
    for (int i = 0; i < 8; i++) {
        int idx = b * NL + i * 256 + tid;
        float s = 0.f;
        #pragma unroll
        for (int p = 0; p < NTILES; p++) s += g_partial[(size_t)p * NROWS + idx];
        v[i] = s;
        mx = fmaxf(mx, s);
    }
    red[tid] = mx; __syncthreads();
    for (int o = 128; o; o >>= 1) { if (tid < o) red[tid] = fmaxf(red[tid], red[tid + o]); __syncthreads(); }
    mx = red[0]; __syncthreads();
    float sum = 0.f;
    #pragma unroll
    for (int i = 0; i < 8; i++) { v[i] = expf(v[i] - mx); sum += v[i]; }
    red[tid] = sum; __syncthreads();
    for (int o = 128; o; o >>= 1) { if (tid < o) red[tid] += red[tid + o]; __syncthreads(); }
    float invs = 1.f / red[0];
    #pragma unroll
    for (int i = 0; i < 8; i++) out[NB * ND + b * NL + i * 256 + tid] = v[i] * invs;
}

// ---------------- K3a: weighted partials over L-chunks (fp16 ctx) ----------------
// block (lc, b), 128 threads: thread t owns d-range [t*8, t*8+8), loops 128 l's.
__global__ void weighted_part(const float* __restrict__ out_attn) {
    __shared__ float sa[NL / LCH];   // 128
    int lc = blockIdx.x, b = blockIdx.y, tid = threadIdx.x;
    for (int i = tid; i < NL / LCH; i += 128)
        sa[i] = out_attn[b * NL + lc * (NL / LCH) + i];
    __syncthreads();
    const uint4* cb = (const uint4*)(g_ctx_h + ((size_t)b * NL + (size_t)lc * (NL / LCH)) * ND) + tid;
    float acc[8] = {0,0,0,0,0,0,0,0};
    #pragma unroll 4
    for (int l = 0; l < NL / LCH; l++) {
        uint4 v = cb[l * (ND / 8)];
        float a = sa[l];
        const __half2* h = (const __half2*)&v;
        #pragma unroll
        for (int q = 0; q < 4; q++) {
            float2 f = __half22float2(h[q]);
            acc[q * 2]     += a * f.x;
            acc[q * 2 + 1] += a * f.y;
        }
    }
    #pragma unroll
    for (int q = 0; q < 8; q += 4)
        *(float4*)(&g_wpart[lc][b][tid * 8 + q]) =
            make_float4(acc[q], acc[q + 1], acc[q + 2], acc[q + 3]);
}

// ---------------- K3b: reduce partials -> out[0 .. NB*ND) ----------------
__global__ void weighted_reduce(float* __restrict__ out) {
    int b = blockIdx.x, tid = threadIdx.x;
    #pragma unroll
    for (int j = 0; j < 4; j++) {
        int d = j * 256 + tid;
        float s = 0.f;
        #pragma unroll
        for (int lc = 0; lc < LCH; lc++) s += g_wpart[lc][b][d];
        out[b * ND + d] = s;
    }
}

// ---------------- launch ----------------
extern "C" void kernel_launch(void* const* d_in, const int* in_sizes, int n_in,
                              void* d_out, int out_size) {
    const float* x   = (const float*)d_in[0];
    const float* ctx = (const float*)d_in[1];
    const float* wa  = (const float*)d_in[2];
    const float* va  = (const float*)d_in[3];
    float* out = (float*)d_out;

    cudaFuncSetAttribute(scores_kernel, cudaFuncAttributeMaxDynamicSharedMemorySize, SMEM_BYTES);

    ctx_convert<<<8192, 256>>>(ctx);
    wb_convert<<<ND, 256>>>(wa);
    ht_kernel<<<NB, 256>>>(x, wa);
    scores_kernel<<<MTILES * NTILES, NTHREADS, SMEM_BYTES>>>(va);
    softmax_kernel<<<NB, 256>>>(out);
    dim3 g3(LCH, NB);
    weighted_part<<<g3, 128>>>(out + NB * ND);
    weighted_reduce<<<NB, 256>>>(out);
}

// round 9
// speedup vs baseline: 2.1451x; 1.7538x over previous
#include <cuda_runtime.h>
#include <cuda_fp16.h>
#include <cstdint>

#define NB 32
#define NL 2048
#define ND 1024
#define NROWS (NB * NL)   // 65536

// scores GEMM tiling
#define BM 128
#define BN 256
#define BK 64
#define NTHREADS 512
#define NKIT (ND / BK)            // 16
#define NSTAGE 3
#define A_BYTES (BM * 128)        // 16 KB
#define B_BYTES (BN * 128)        // 32 KB
#define STAGE_BYTES (A_BYTES + B_BYTES)
#define SMEM_BYTES (NSTAGE * STAGE_BYTES)   // 144 KB
#define NTILES (ND / BN)          // 4
#define MTILES (NROWS / BM)       // 512

#define LCH 16                    // weighted split-L chunks

// ---------------- scratch ----------------
__device__ __half g_ctx_h[(size_t)NROWS * ND];   // 128 MB
__device__ __half g_wb_h[ND * ND];               // 2 MB (Wa_s * 64, [n][d])
__device__ float g_ht[NB * ND];                  // 128 KB
__device__ float g_partial[NTILES * NROWS];      // 1 MB
__device__ float g_wpart[LCH][NB][ND];           // 2 MB

// ---------------- helpers ----------------
__device__ __forceinline__ uint32_t smem_u32(const void* p) {
    uint32_t a;
    asm("{ .reg .u64 t; cvta.to.shared.u64 t, %1; cvt.u32.u64 %0, t; }" : "=r"(a) : "l"(p));
    return a;
}
__device__ __forceinline__ void cpa16(uint32_t dst, const void* src) {
    asm volatile("cp.async.cg.shared.global [%0], [%1], 16;" :: "r"(dst), "l"(src));
}
__device__ __forceinline__ void cpa_commit() {
    asm volatile("cp.async.commit_group;" ::: "memory");
}
__device__ __forceinline__ void cpa_wait1() {
    asm volatile("cp.async.wait_group 1;" ::: "memory");
}
__device__ __forceinline__ void ldsm4(uint32_t* r, uint32_t addr) {
    asm volatile("ldmatrix.sync.aligned.m8n8.x4.shared.b16 {%0,%1,%2,%3}, [%4];"
                 : "=r"(r[0]), "=r"(r[1]), "=r"(r[2]), "=r"(r[3]) : "r"(addr));
}
__device__ __forceinline__ void mma16816(float* c, const uint32_t* a, uint32_t b0, uint32_t b1) {
    asm volatile("mma.sync.aligned.m16n8k16.row.col.f32.f16.f16.f32 "
                 "{%0,%1,%2,%3}, {%4,%5,%6,%7}, {%8,%9}, {%0,%1,%2,%3};"
                 : "+f"(c[0]), "+f"(c[1]), "+f"(c[2]), "+f"(c[3])
                 : "r"(a[0]), "r"(a[1]), "r"(a[2]), "r"(a[3]), "r"(b0), "r"(b1));
}
__device__ __forceinline__ uint32_t pack2(float a, float b) {
    __half2 h = __floats2half2_rn(a, b);
    return *reinterpret_cast<uint32_t*>(&h);
}

// ---------------- P0: convert context fp32 -> fp16 (high-MLP stream) ----------------
__global__ void ctx_convert(const float* __restrict__ ctx) {
    size_t base = (size_t)blockIdx.x * 256 + threadIdx.x;    // 8192 blocks
    const float4* src = (const float4*)ctx;
    uint2* dst = (uint2*)g_ctx_h;
    #pragma unroll
    for (int j = 0; j < 8; j++) {
        size_t g = base + (size_t)j * 2097152;               // 16M float4 groups
        float4 v = src[g];
        dst[g] = make_uint2(pack2(v.x, v.y), pack2(v.z, v.w));
    }
}

// ---------------- P1: convert Wa_s (scaled x64) -> fp16 ----------------
__global__ void wb_convert(const float* __restrict__ wa) {
    int n = blockIdx.x;
    const float* src = wa + (size_t)n * (2 * ND) + ND + threadIdx.x * 4;
    float4 v = *(const float4*)src;
    uint2* dst = (uint2*)(g_wb_h + (size_t)n * ND);
    dst[threadIdx.x] = make_uint2(pack2(v.x * 64.f, v.y * 64.f),
                                  pack2(v.z * 64.f, v.w * 64.f));
}

// ---------------- K0: ht_proj[b,k] = sum_d x[b,d]*Wa[k,d] (fp32) ----------------
// grid (NB, 8): block handles 128 k's for one b -> 256 blocks.
__global__ void ht_kernel(const float* __restrict__ x, const float* __restrict__ wa) {
    int b = blockIdx.x, kb = blockIdx.y * 128;
    int warp = threadIdx.x >> 5, lane = threadIdx.x & 31;
    const float* xr = x + b * ND;
    for (int k = kb + warp; k < kb + 128; k += 8) {
        const float* wr = wa + (size_t)k * (2 * ND);
        float acc = 0.f;
        #pragma unroll 8
        for (int d = lane; d < ND; d += 32) acc += xr[d] * wr[d];
        #pragma unroll
        for (int o = 16; o; o >>= 1) acc += __shfl_xor_sync(0xFFFFFFFFu, acc, o);
        if (lane == 0) g_ht[b * ND + k] = acc;
    }
}

// ---------------- K1: scores partials via fp16 mma.sync GEMM ----------------
// grid 2048: mtile = bid>>2, ntile = bid&3. 512 thr, warps 4x4, warp tile 32x64,
// BK=64, 3-stage cp.async.
__global__ void __launch_bounds__(NTHREADS, 1) scores_kernel(const float* __restrict__ va) {
    extern __shared__ char smem[];
    const uint32_t sbase = smem_u32(smem);

    const int tid = threadIdx.x;
    const int lane = tid & 31, wid = tid >> 5;
    const int wm = wid >> 2, wn = wid & 3;       // 4 x 4 warps
    const int g = lane >> 2, tig = lane & 3;
    const int lane7 = lane & 7;
    const int cSelA = lane >> 4;                 // 0/1
    const int cSelB = (lane >> 3) & 1;           // 0/1

    const int mtile = blockIdx.x >> 2, ntile = blockIdx.x & 3;
    const int rbase = mtile * BM;
    const int nbase = ntile * BN;
    const int b = rbase >> 11;

    const __half* gA = g_ctx_h + (size_t)rbase * ND;
    const __half* gB = g_wb_h + (size_t)nbase * ND;

    // cp.async per-thread assignments (512 thr: A 2 chunks, B 4 chunks)
    uint32_t aDst[2], bDst[4];
    uint32_t aSrcOff[2], bSrcOff[4];
    #pragma unroll
    for (int i = 0; i < 2; i++) {
        int id = tid * 2 + i, row = id >> 3, c = id & 7;
        aDst[i] = row * 128 + ((c ^ (row & 7)) << 4);
        aSrcOff[i] = row * ND + c * 8;
    }
    #pragma unroll
    for (int i = 0; i < 4; i++) {
        int id = tid * 4 + i, row = id >> 3, c = id & 7;
        bDst[i] = A_BYTES + row * 128 + ((c ^ (row & 7)) << 4);
        bSrcOff[i] = row * ND + c * 8;
    }

    // ldmatrix base offsets: warp rows wm*32 + mt*16, warp cols wn*64
    const int aRow = wm * 32 + ((lane >> 3) & 1) * 8 + lane7;
    const uint32_t aOff = (uint32_t)aRow * 128;
    uint32_t bOff[4];
    #pragma unroll
    for (int i = 0; i < 4; i++)
        bOff[i] = (uint32_t)(wn * 64 + i * 16 + ((lane >> 4) & 1) * 8 + lane7) * 128 + A_BYTES;

    float c[2][8][4];
    #pragma unroll
    for (int i = 0; i < 2; i++)
        #pragma unroll
        for (int j = 0; j < 8; j++)
            #pragma unroll
            for (int q = 0; q < 4; q++) c[i][j][q] = 0.f;

    // prologue: fill stages 0,1
    #pragma unroll
    for (int s = 0; s < 2; s++) {
        uint32_t st = sbase + s * STAGE_BYTES;
        const __half* a = gA + s * BK;
        const __half* bb = gB + s * BK;
        #pragma unroll
        for (int i = 0; i < 2; i++) cpa16(st + aDst[i], a + aSrcOff[i]);
        #pragma unroll
        for (int i = 0; i < 4; i++) cpa16(st + bDst[i], bb + bSrcOff[i]);
        cpa_commit();
    }

    int stage = 0;
    for (int ck = 0; ck < NKIT; ck++) {
        cpa_wait1();
        __syncthreads();

        // issue k-chunk ck+2 into stage (stage+2)%3
        if (ck + 2 < NKIT) {
            int s2 = stage + 2; if (s2 >= 3) s2 -= 3;
            uint32_t st = sbase + s2 * STAGE_BYTES;
            const __half* a = gA + (ck + 2) * BK;
            const __half* bb = gB + (ck + 2) * BK;
            #pragma unroll
            for (int i = 0; i < 2; i++) cpa16(st + aDst[i], a + aSrcOff[i]);
            #pragma unroll
            for (int i = 0; i < 4; i++) cpa16(st + bDst[i], bb + bSrcOff[i]);
        }
        cpa_commit();

        const uint32_t sA = sbase + stage * STAGE_BYTES;
        #pragma unroll
        for (int ks = 0; ks < 4; ks++) {
            uint32_t aSwz = (uint32_t)(((ks * 2 + cSelA) ^ lane7) << 4);
            uint32_t bSwz = (uint32_t)(((ks * 2 + cSelB) ^ lane7) << 4);
            uint32_t af[2][4], bf[4][4];
            #pragma unroll
            for (int mt = 0; mt < 2; mt++)
                ldsm4(af[mt], sA + aOff + mt * 2048 + aSwz);
            #pragma unroll
            for (int i = 0; i < 4; i++)
                ldsm4(bf[i], sA + bOff[i] + bSwz);
            #pragma unroll
            for (int mt = 0; mt < 2; mt++)
                #pragma unroll
                for (int n8 = 0; n8 < 8; n8++)
                    mma16816(c[mt][n8], af[mt], bf[n8 >> 1][(n8 & 1) * 2],
                             bf[n8 >> 1][(n8 & 1) * 2 + 1]);
        }
        stage++; if (stage >= 3) stage = 0;
    }
    __syncthreads();

    // ---- epilogue: p[row] = sum_col va[k]*tanh(ht[b,k] + C/64), cross-wn smem reduce ----
    float* sht  = (float*)smem;                 // [BN]
    float* sva  = sht + BN;                     // [BN]
    float* sred = sva + BN;                     // [4][BM]
    for (int i = tid; i < BN; i += NTHREADS) {
        sht[i] = g_ht[b * ND + nbase + i];
        sva[i] = va[nbase + i];
    }
    __syncthreads();

    const float inv = 1.0f / 64.0f;
    #pragma unroll
    for (int mt = 0; mt < 2; mt++) {
        float p0 = 0.f, p1 = 0.f;
        #pragma unroll
        for (int n8 = 0; n8 < 8; n8++) {
            #pragma unroll
            for (int j = 0; j < 2; j++) {
                int col = wn * 64 + n8 * 8 + tig * 2 + j;
                float hv = sht[col], vv = sva[col];
                p0 += vv * tanhf(hv + c[mt][n8][j] * inv);
                p1 += vv * tanhf(hv + c[mt][n8][2 + j] * inv);
            }
        }
        p0 += __shfl_xor_sync(0xFFFFFFFFu, p0, 1);
        p0 += __shfl_xor_sync(0xFFFFFFFFu, p0, 2);
        p1 += __shfl_xor_sync(0xFFFFFFFFu, p1, 1);
        p1 += __shfl_xor_sync(0xFFFFFFFFu, p1, 2);
        if (tig == 0) {
            int rl = wm * 32 + mt * 16 + g;
            sred[wn * BM + rl]     = p0;
            sred[wn * BM + rl + 8] = p1;
        }
    }
    __syncthreads();
    for (int i = tid; i < BM; i += NTHREADS) {
        float s = sred[i] + sred[BM + i] + sred[2 * BM + i] + sred[3 * BM + i];
        g_partial[(size_t)ntile * NROWS + rbase + i] = s;
    }
}

// ---------------- K2: sum partials + softmax -> out[NB*ND ..] ----------------
__global__ void softmax_kernel(float* __restrict__ out) {
    __shared__ float red[256];
    int b = blockIdx.x, tid = threadIdx.x;
    float v[8], mx = -1e30f;
    #pragma unroll
    for (int i = 0; i < 8; i++) {
        int idx = b * NL + i * 256 + tid;
        float s = 0.f;
        #pragma unroll
        for (int p = 0; p < NTILES; p++) s += g_partial[(size_t)p * NROWS + idx];
        v[i] = s;
        mx = fmaxf(mx, s);
    }
    red[tid] = mx; __syncthreads();
    for (int o = 128; o; o >>= 1) { if (tid < o) red[tid] = fmaxf(red[tid], red[tid + o]); __syncthreads(); }
    mx = red[0]; __syncthreads();
    float sum = 0.f;
    #pragma unroll
    for (int i = 0; i < 8; i++) { v[i] = expf(v[i] - mx); sum += v[i]; }
    red[tid] = sum; __syncthreads();
    for (int o = 128; o; o >>= 1) { if (tid < o) red[tid] += red[tid + o]; __syncthreads(); }
    float invs = 1.f / red[0];
    #pragma unroll
    for (int i = 0; i < 8; i++) out[NB * ND + b * NL + i * 256 + tid] = v[i] * invs;
}

// ---------------- K3a: weighted partials over L-chunks (fp16 ctx) ----------------
__global__ void weighted_part(const float* __restrict__ out_attn) {
    __shared__ float sa[NL / LCH];   // 128
    int lc = blockIdx.x, b = blockIdx.y, tid = threadIdx.x;
    for (int i = tid; i < NL / LCH; i += 128)
        sa[i] = out_attn[b * NL + lc * (NL / LCH) + i];
    __syncthreads();
    const uint4* cb = (const uint4*)(g_ctx_h + ((size_t)b * NL + (size_t)lc * (NL / LCH)) * ND) + tid;
    float acc[8] = {0,0,0,0,0,0,0,0};
    #pragma unroll 4
    for (int l = 0; l < NL / LCH; l++) {
        uint4 v = cb[l * (ND / 8)];
        float a = sa[l];
        const __half2* h = (const __half2*)&v;
        #pragma unroll
        for (int q = 0; q < 4; q++) {
            float2 f = __half22float2(h[q]);
            acc[q * 2]     += a * f.x;
            acc[q * 2 + 1] += a * f.y;
        }
    }
    #pragma unroll
    for (int q = 0; q < 8; q += 4)
        *(float4*)(&g_wpart[lc][b][tid * 8 + q]) =
            make_float4(acc[q], acc[q + 1], acc[q + 2], acc[q + 3]);
}

// ---------------- K3b: reduce partials -> out[0 .. NB*ND) ----------------
__global__ void weighted_reduce(float* __restrict__ out) {
    int b = blockIdx.x, tid = threadIdx.x;
    #pragma unroll
    for (int j = 0; j < 4; j++) {
        int d = j * 256 + tid;
        float s = 0.f;
        #pragma unroll
        for (int lc = 0; lc < LCH; lc++) s += g_wpart[lc][b][d];
        out[b * ND + d] = s;
    }
}

// ---------------- launch ----------------
extern "C" void kernel_launch(void* const* d_in, const int* in_sizes, int n_in,
                              void* d_out, int out_size) {
    const float* x   = (const float*)d_in[0];
    const float* ctx = (const float*)d_in[1];
    const float* wa  = (const float*)d_in[2];
    const float* va  = (const float*)d_in[3];
    float* out = (float*)d_out;

    cudaFuncSetAttribute(scores_kernel, cudaFuncAttributeMaxDynamicSharedMemorySize, SMEM_BYTES);

    ctx_convert<<<8192, 256>>>(ctx);
    wb_convert<<<ND, 256>>>(wa);
    dim3 gh(NB, 8);
    ht_kernel<<<gh, 256>>>(x, wa);
    scores_kernel<<<MTILES * NTILES, NTHREADS, SMEM_BYTES>>>(va);
    softmax_kernel<<<NB, 256>>>(out);
    dim3 g3(LCH, NB);
    weighted_part<<<g3, 128>>>(out + NB * ND);
    weighted_reduce<<<NB, 256>>>(out);
}